// round 13
// baseline (speedup 1.0000x reference)
#include <cuda_runtime.h>
#include <cuda_fp16.h>
#include <math.h>
#include <stdint.h>

#define SEQ   2048
#define BATCH 2
#define DM    1024
#define NH    16
#define HD    64
#define DFF   4096
#define T_    (SEQ*BATCH)

// ---------------- scratch (no allocations allowed) ----------------
__device__ __half g_h  [T_*DM];
__device__ float  g_q  [BATCH*NH*SEQ*HD];
__device__ float  g_k  [BATCH*NH*SEQ*HD];
__device__ float  g_v  [BATCH*NH*SEQ*HD];
__device__ __half g_ctx[T_*DM];
__device__ float  g_x1 [T_*DM];
__device__ __half g_h2 [T_*DM];
__device__ __half g_ff [T_*DFF];
// transposed fp16 weights [N][K]
__device__ __half g_wqkvt[3*DM*DM];
__device__ __half g_wot  [DM*DM];
__device__ __half g_w1t  [DFF*DM];
__device__ __half g_w2t  [DM*DFF];

// ---------------- helpers ----------------
__device__ __forceinline__ void mma_f16(float c[4], const uint32_t a[4], const uint32_t b[2]) {
    asm volatile(
        "mma.sync.aligned.m16n8k16.row.col.f32.f16.f16.f32 "
        "{%0,%1,%2,%3}, {%4,%5,%6,%7}, {%8,%9}, {%0,%1,%2,%3};"
        : "+f"(c[0]), "+f"(c[1]), "+f"(c[2]), "+f"(c[3])
        : "r"(a[0]), "r"(a[1]), "r"(a[2]), "r"(a[3]), "r"(b[0]), "r"(b[1]));
}
__device__ __forceinline__ void cp16(uint32_t dst, const void* src) {
    asm volatile("cp.async.cg.shared.global [%0], [%1], 16;" :: "r"(dst), "l"(src));
}
__device__ __forceinline__ void ldsm4(uint32_t r[4], uint32_t addr) {
    asm volatile("ldmatrix.sync.aligned.m8n8.x4.shared.b16 {%0,%1,%2,%3}, [%4];"
        : "=r"(r[0]), "=r"(r[1]), "=r"(r[2]), "=r"(r[3]) : "r"(addr));
}
__device__ __forceinline__ uint32_t h2u(__half2 h) { return *(const uint32_t*)&h; }

// ---------------- RMSNorm (fp32 in, fp16 out), vectorized ----------------
__global__ void rmsnorm_kernel(const float* __restrict__ x, const float* __restrict__ g,
                               __half* __restrict__ o) {
    int row = blockIdx.x;
    float4 v = ((const float4*)(x + (size_t)row * DM))[threadIdx.x];
    float s = v.x * v.x + v.y * v.y + v.z * v.z + v.w * v.w;
    __shared__ float red[8];
    for (int off = 16; off; off >>= 1) s += __shfl_xor_sync(0xffffffffu, s, off);
    if ((threadIdx.x & 31) == 0) red[threadIdx.x >> 5] = s;
    __syncthreads();
    if (threadIdx.x < 8) {
        float t = red[threadIdx.x];
        for (int off = 4; off; off >>= 1) t += __shfl_xor_sync(0xffu, t, off);
        if (threadIdx.x == 0) red[0] = t;
    }
    __syncthreads();
    float inv = rsqrtf(red[0] * (1.f / DM) + 1e-6f);
    float4 gv = ((const float4*)g)[threadIdx.x];
    __half2 h01 = __floats2half2_rn(gv.x * v.x * inv, gv.y * v.y * inv);
    __half2 h23 = __floats2half2_rn(gv.z * v.z * inv, gv.w * v.w * inv);
    uint2 st;
    st.x = h2u(h01);
    st.y = h2u(h23);
    *(uint2*)(o + (size_t)row * DM + threadIdx.x * 4) = st;
}

// ---------------- weight transposes (fp32 -> fp16, out[n][k] = in[k][n]) ----------------
__global__ void tr_plain(const float* __restrict__ in, __half* __restrict__ out,
                         int K, int N) {
    __shared__ float tile[32][33];
    int n0 = blockIdx.x << 5, k0 = blockIdx.y << 5;
    int tx = threadIdx.x, ty = threadIdx.y;
#pragma unroll
    for (int j = 0; j < 32; j += 8)
        tile[ty + j][tx] = in[(size_t)(k0 + ty + j) * N + n0 + tx];
    __syncthreads();
#pragma unroll
    for (int j = 0; j < 32; j += 8)
        out[(size_t)(n0 + ty + j) * K + k0 + tx] = __float2half_rn(tile[tx][ty + j]);
}
__global__ void tr_qkv(const float* __restrict__ Wq, const float* __restrict__ Wk,
                       const float* __restrict__ Wv, __half* __restrict__ out) {
    __shared__ float tile[32][33];
    int n0 = blockIdx.x << 5, k0 = blockIdx.y << 5;
    int which = n0 >> 10;
    const float* W = (which == 0) ? Wq : ((which == 1) ? Wk : Wv);
    int h = (n0 >> 6) & 15;
    int kk0 = n0 & 63;
    int tx = threadIdx.x, ty = threadIdx.y;
#pragma unroll
    for (int j = 0; j < 32; j += 8)
        tile[ty + j][tx] = W[(size_t)h * DM * HD + (size_t)(k0 + ty + j) * HD + kk0 + tx];
    __syncthreads();
#pragma unroll
    for (int j = 0; j < 32; j += 8)
        out[(size_t)(n0 + ty + j) * DM + k0 + tx] = __float2half_rn(tile[tx][ty + j]);
}

// ---- fp16 GEMM: 128x128 tile, 8 warps of 32x64, k-tile 32, cp.async + ldmatrix ----
#define PW 36
#define TILEW (128*PW)
#define G16_SMEM (4*TILEW*4)

template<int MODE>  // 1 = SiLU->half, 2 = +Res->float, 3 = QKV scatter->float
__global__ __launch_bounds__(256, 2) void tgemm16(
        const __half* __restrict__ A, const __half* __restrict__ Bt,
        const float* __restrict__ Res,
        float* __restrict__ F0, float* __restrict__ F1, float* __restrict__ F2,
        __half* __restrict__ H0,
        int M, int N, int Kd) {
    extern __shared__ uint32_t dsm[];
    int tid = threadIdx.x;
    int row0 = blockIdx.y << 7, col0 = blockIdx.x << 7;
    int lane = tid & 31, warp = tid >> 5;
    int wm = (warp & 3) << 5;
    int wn = (warp >> 2) << 6;
    int g = lane >> 2, t = lane & 3;

    int lr = tid >> 1;
    int lc = (tid & 1) << 1;
    const __half* Ap = A  + (size_t)(row0 + lr) * Kd + lc * 8;
    const __half* Bp = Bt + (size_t)(col0 + lr) * Kd + lc * 8;

    uint32_t s0 = (uint32_t)__cvta_generic_to_shared(dsm);
    uint32_t aoff = s0 + (lr * PW + lc * 4) * 4;
    uint32_t boff = aoff + 2 * TILEW * 4;

    uint32_t a_frag = s0 + (((wm + (lane & 15)) * PW) + ((lane >> 4) << 2)) * 4;
    uint32_t b_frag = s0 + 2 * TILEW * 4 +
                      (((wn + (lane & 7) + (((lane >> 4) & 1) << 3)) * PW) +
                       (((lane >> 3) & 1) << 2)) * 4;

    float acc[2][8][4];
#pragma unroll
    for (int i = 0; i < 2; i++)
#pragma unroll
        for (int j = 0; j < 8; j++)
#pragma unroll
            for (int v = 0; v < 4; v++) acc[i][j][v] = 0.f;

    int KT = Kd >> 5;
#pragma unroll
    for (int u = 0; u < 2; u++) {
        cp16(aoff + u * 16, Ap + u * 8);
        cp16(boff + u * 16, Bp + u * 8);
    }
    asm volatile("cp.async.commit_group;");

    for (int kt = 0; kt < KT; kt++) {
        int sel = kt & 1;
        if (kt + 1 < KT) {
            int k0 = (kt + 1) << 5;
            uint32_t ad = aoff + (sel ^ 1) * (TILEW * 4);
            uint32_t bd = boff + (sel ^ 1) * (TILEW * 4);
#pragma unroll
            for (int u = 0; u < 2; u++) {
                cp16(ad + u * 16, Ap + k0 + u * 8);
                cp16(bd + u * 16, Bp + k0 + u * 8);
            }
            asm volatile("cp.async.commit_group;");
            asm volatile("cp.async.wait_group 1;");
        } else {
            asm volatile("cp.async.wait_group 0;");
        }
        __syncthreads();
        uint32_t abase = a_frag + sel * (TILEW * 4);
        uint32_t bbase = b_frag + sel * (TILEW * 4);
#pragma unroll
        for (int ks = 0; ks < 2; ks++) {
            uint32_t kb = ks * 8 * 4;
            uint32_t af[2][4];
            ldsm4(af[0], abase + kb);
            ldsm4(af[1], abase + kb + 16 * PW * 4);
#pragma unroll
            for (int p = 0; p < 4; p++) {
                uint32_t br[4];
                ldsm4(br, bbase + kb + p * 16 * PW * 4);
                mma_f16(acc[0][2 * p],     af[0], &br[0]);
                mma_f16(acc[0][2 * p + 1], af[0], &br[2]);
                mma_f16(acc[1][2 * p],     af[1], &br[0]);
                mma_f16(acc[1][2 * p + 1], af[1], &br[2]);
            }
        }
        __syncthreads();
    }

    // epilogue
#pragma unroll
    for (int mt = 0; mt < 2; mt++) {
#pragma unroll
        for (int nt = 0; nt < 8; nt++) {
            int r = row0 + wm + mt * 16 + g;
            int c = col0 + wn + nt * 8 + t * 2;
            float2 v0 = make_float2(acc[mt][nt][0], acc[mt][nt][1]);
            float2 v1 = make_float2(acc[mt][nt][2], acc[mt][nt][3]);
            if (MODE == 3) {
                int which = c >> 10, hh = (c >> 6) & 15, kk = c & 63;
                float* O = (which == 0) ? F0 : ((which == 1) ? F1 : F2);
                int b = r & 1;
                int sq0 = r >> 1, sq1 = (r + 8) >> 1;
                *(float2*)(O + ((size_t)(b * NH + hh) * SEQ + sq0) * HD + kk) = v0;
                *(float2*)(O + ((size_t)(b * NH + hh) * SEQ + sq1) * HD + kk) = v1;
            } else if (MODE == 1) {
                float a0 = v0.x / (1.f + __expf(-v0.x));
                float a1 = v0.y / (1.f + __expf(-v0.y));
                float a2 = v1.x / (1.f + __expf(-v1.x));
                float a3 = v1.y / (1.f + __expf(-v1.y));
                *(__half2*)(H0 + (size_t)r * N + c)       = __floats2half2_rn(a0, a1);
                *(__half2*)(H0 + (size_t)(r + 8) * N + c) = __floats2half2_rn(a2, a3);
            } else {
                size_t i0 = (size_t)r * N + c;
                size_t i1 = (size_t)(r + 8) * N + c;
                float2 e0 = *(const float2*)&Res[i0];
                float2 e1 = *(const float2*)&Res[i1];
                v0.x += e0.x; v0.y += e0.y;
                v1.x += e1.x; v1.y += e1.y;
                *(float2*)&F0[i0] = v0;
                *(float2*)&F0[i1] = v1;
            }
        }
    }
}

// ---------------- flash attention, fp16 mma inside (fp32 q/k/v in gmem) ----------------
// word regions: Qs[64*36] Ks[64*36] Ps[64*36] VsT[64*33] Ss_f32[64*68] stats[192]
#define AQP 36
#define AVP 33
#define ASP 68
#define ATTN_SMEM_BYTES ((3*64*AQP + 64*AVP + 64*ASP + 192) * 4)

__global__ __launch_bounds__(256, 2) void attn_kernel(
        const float* __restrict__ Q, const float* __restrict__ K,
        const float* __restrict__ V, __half* __restrict__ ctx) {
    extern __shared__ uint32_t aw[];
    uint32_t* Qs  = aw;
    uint32_t* Ks  = Qs + 64 * AQP;
    uint32_t* Ps  = Ks + 64 * AQP;
    uint32_t* VsT = Ps + 64 * AQP;
    float*    Ss  = (float*)(VsT + 64 * AVP);
    float* sm_m = Ss + 64 * ASP;
    float* sm_l = sm_m + 64;
    float* sm_a = sm_l + 64;

    int s0 = blockIdx.x * 64, hh = blockIdx.y, b = blockIdx.z;
    int tid = threadIdx.x;
    int lane = tid & 31, warp = tid >> 5;
    int wm = (warp & 3) << 4;   // 0,16,32,48
    int wn = (warp >> 2) << 5;  // 0,32
    int g = lane >> 2, t = lane & 3;
    const size_t bh = ((size_t)b * NH + hh) * SEQ * HD;
    const float* Qp = Q + bh;
    const float* Kp = K + bh;
    const float* Vp = V + bh;

    // load Q tile, scale, convert fp16
    {
        int r = tid >> 2, c4 = (tid & 3) << 4;
        const float sc = 0.125f;
#pragma unroll
        for (int u = 0; u < 4; u++) {
            float4 qv = *(const float4*)&Qp[(size_t)(s0 + r) * HD + c4 + u * 4];
            Qs[r * AQP + (c4 >> 1) + 2 * u]     = h2u(__floats2half2_rn(qv.x * sc, qv.y * sc));
            Qs[r * AQP + (c4 >> 1) + 2 * u + 1] = h2u(__floats2half2_rn(qv.z * sc, qv.w * sc));
        }
    }
    if (tid < 64) { sm_m[tid] = -1e30f; sm_l[tid] = 0.f; }

    float oacc[4][4];
#pragma unroll
    for (int nt = 0; nt < 4; nt++)
#pragma unroll
        for (int v = 0; v < 4; v++) oacc[nt][v] = 0.f;

    for (int j0 = 0; j0 <= s0; j0 += 64) {
        __syncthreads();   // protect Ks/VsT/Ps reuse (and Q/stat init)
        // K tile [key][hd] fp16
        {
            int r = tid >> 2, c4 = (tid & 3) << 4;
#pragma unroll
            for (int u = 0; u < 4; u++) {
                float4 kv = *(const float4*)&Kp[(size_t)(j0 + r) * HD + c4 + u * 4];
                Ks[r * AQP + (c4 >> 1) + 2 * u]     = h2u(__floats2half2_rn(kv.x, kv.y));
                Ks[r * AQP + (c4 >> 1) + 2 * u + 1] = h2u(__floats2half2_rn(kv.z, kv.w));
            }
        }
        // V tile transposed: VsT[hd][key-pair] half2 = (V[2kp][h], V[2kp+1][h])
        {
            int kp = tid >> 3, hc = tid & 7;
            const float* v0p = Vp + (size_t)(j0 + 2 * kp) * HD + hc * 8;
            const float* v1p = v0p + HD;
            float4 a0 = *(const float4*)v0p;
            float4 a1 = *(const float4*)(v0p + 4);
            float4 c0v = *(const float4*)v1p;
            float4 c1v = *(const float4*)(v1p + 4);
            const float* av = (const float*)&a0;  // a0,a1 contiguous? not guaranteed; use arrays
            float va[8] = {a0.x, a0.y, a0.z, a0.w, a1.x, a1.y, a1.z, a1.w};
            float vc[8] = {c0v.x, c0v.y, c0v.z, c0v.w, c1v.x, c1v.y, c1v.z, c1v.w};
            (void)av;
#pragma unroll
            for (int i = 0; i < 8; i++)
                VsT[(hc * 8 + i) * AVP + kp] = h2u(__floats2half2_rn(va[i], vc[i]));
        }
        __syncthreads();
        // S = Q @ K^T (fp16 mma, 4 k16 steps)
        float sacc[4][4];
#pragma unroll
        for (int nt = 0; nt < 4; nt++)
#pragma unroll
            for (int v = 0; v < 4; v++) sacc[nt][v] = 0.f;
#pragma unroll
        for (int ks = 0; ks < 4; ks++) {
            int ksw = ks * 8;
            uint32_t af[4];
            af[0] = Qs[(wm + g) * AQP + ksw + t];
            af[1] = Qs[(wm + g + 8) * AQP + ksw + t];
            af[2] = Qs[(wm + g) * AQP + ksw + t + 4];
            af[3] = Qs[(wm + g + 8) * AQP + ksw + t + 4];
#pragma unroll
            for (int nt = 0; nt < 4; nt++) {
                int cb = wn + nt * 8 + g;
                uint32_t bf[2];
                bf[0] = Ks[cb * AQP + ksw + t];
                bf[1] = Ks[cb * AQP + ksw + t + 4];
                mma_f16(sacc[nt], af, bf);
            }
        }
        // mask (diagonal) + store S fp32
        {
            bool diag = (j0 == s0);
            int r0 = wm + g, r1 = wm + g + 8;
#pragma unroll
            for (int nt = 0; nt < 4; nt++) {
                int c0 = wn + nt * 8 + t * 2;
                float2 v0 = make_float2(sacc[nt][0], sacc[nt][1]);
                float2 v1 = make_float2(sacc[nt][2], sacc[nt][3]);
                if (diag) {
                    if (c0 > r0)     v0.x = -1e30f;
                    if (c0 + 1 > r0) v0.y = -1e30f;
                    if (c0 > r1)     v1.x = -1e30f;
                    if (c0 + 1 > r1) v1.y = -1e30f;
                }
                *(float2*)&Ss[r0 * ASP + c0] = v0;
                *(float2*)&Ss[r1 * ASP + c0] = v1;
            }
        }
        __syncthreads();
        // online softmax (4 threads/row); write P as fp16 pairs (no big array)
        {
            int r = tid >> 2, c0 = (tid & 3) << 4;
            float mx = -1e30f;
#pragma unroll
            for (int c = 0; c < 16; c++) mx = fmaxf(mx, Ss[r * ASP + c0 + c]);
            mx = fmaxf(mx, __shfl_xor_sync(0xffffffffu, mx, 1));
            mx = fmaxf(mx, __shfl_xor_sync(0xffffffffu, mx, 2));
            float m_old = sm_m[r];
            float m_new = fmaxf(m_old, mx);
            float sum = 0.f;
#pragma unroll
            for (int c = 0; c < 16; c += 2) {
                float p0 = __expf(Ss[r * ASP + c0 + c]     - m_new);
                float p1 = __expf(Ss[r * ASP + c0 + c + 1] - m_new);
                sum += p0 + p1;
                Ps[r * AQP + ((c0 + c) >> 1)] = h2u(__floats2half2_rn(p0, p1));
            }
            sum += __shfl_xor_sync(0xffffffffu, sum, 1);
            sum += __shfl_xor_sync(0xffffffffu, sum, 2);
            if ((tid & 3) == 0) {
                float alpha = __expf(m_old - m_new);
                sm_a[r] = alpha;
                sm_m[r] = m_new;
                sm_l[r] = sm_l[r] * alpha + sum;
            }
        }
        __syncthreads();
        // rescale O, then O += P @ V (fp16 mma)
        {
            float al0 = sm_a[wm + g], al1 = sm_a[wm + g + 8];
#pragma unroll
            for (int nt = 0; nt < 4; nt++) {
                oacc[nt][0] *= al0; oacc[nt][1] *= al0;
                oacc[nt][2] *= al1; oacc[nt][3] *= al1;
            }
        }
#pragma unroll
        for (int ks = 0; ks < 4; ks++) {
            int ksw = ks * 8;
            uint32_t af[4];
            af[0] = Ps[(wm + g) * AQP + ksw + t];
            af[1] = Ps[(wm + g + 8) * AQP + ksw + t];
            af[2] = Ps[(wm + g) * AQP + ksw + t + 4];
            af[3] = Ps[(wm + g + 8) * AQP + ksw + t + 4];
#pragma unroll
            for (int nt = 0; nt < 4; nt++) {
                int cb = wn + nt * 8 + g;
                uint32_t bf[2];
                bf[0] = VsT[cb * AVP + ksw + t];
                bf[1] = VsT[cb * AVP + ksw + t + 4];
                mma_f16(oacc[nt], af, bf);
            }
        }
    }
    // normalize, write ctx (S,B,D) head-concat, fp16
    {
        float inv0 = 1.f / sm_l[wm + g];
        float inv1 = 1.f / sm_l[wm + g + 8];
        int r0 = s0 + wm + g, r1 = s0 + wm + g + 8;
#pragma unroll
        for (int nt = 0; nt < 4; nt++) {
            int c0 = hh * HD + wn + nt * 8 + t * 2;
            *(__half2*)&ctx[((size_t)r0 * BATCH + b) * DM + c0] =
                __floats2half2_rn(oacc[nt][0] * inv0, oacc[nt][1] * inv0);
            *(__half2*)&ctx[((size_t)r1 * BATCH + b) * DM + c0] =
                __floats2half2_rn(oacc[nt][2] * inv1, oacc[nt][3] * inv1);
        }
    }
}

// ---------------- launch ----------------
extern "C" void kernel_launch(void* const* d_in, const int* in_sizes, int n_in,
                              void* d_out, int out_size) {
    const float* x  = (const float*)d_in[0];
    const float* g1 = (const float*)d_in[1];
    const float* g2 = (const float*)d_in[2];
    const float* Wq = (const float*)d_in[3];
    const float* Wk = (const float*)d_in[4];
    const float* Wv = (const float*)d_in[5];
    const float* Wo = (const float*)d_in[6];
    const float* W1 = (const float*)d_in[7];
    const float* W2 = (const float*)d_in[8];
    float* out = (float*)d_out;

    __half *h, *ctx, *h2, *ff, *wqkvt, *wot, *w1t, *w2t;
    float *q, *k, *v, *x1;
    cudaGetSymbolAddress((void**)&h,   g_h);
    cudaGetSymbolAddress((void**)&q,   g_q);
    cudaGetSymbolAddress((void**)&k,   g_k);
    cudaGetSymbolAddress((void**)&v,   g_v);
    cudaGetSymbolAddress((void**)&ctx, g_ctx);
    cudaGetSymbolAddress((void**)&x1,  g_x1);
    cudaGetSymbolAddress((void**)&h2,  g_h2);
    cudaGetSymbolAddress((void**)&ff,  g_ff);
    cudaGetSymbolAddress((void**)&wqkvt, g_wqkvt);
    cudaGetSymbolAddress((void**)&wot,   g_wot);
    cudaGetSymbolAddress((void**)&w1t,   g_w1t);
    cudaGetSymbolAddress((void**)&w2t,   g_w2t);

    cudaFuncSetAttribute(attn_kernel, cudaFuncAttributeMaxDynamicSharedMemorySize, ATTN_SMEM_BYTES);
    cudaFuncSetAttribute(tgemm16<1>, cudaFuncAttributeMaxDynamicSharedMemorySize, G16_SMEM);
    cudaFuncSetAttribute(tgemm16<2>, cudaFuncAttributeMaxDynamicSharedMemorySize, G16_SMEM);
    cudaFuncSetAttribute(tgemm16<3>, cudaFuncAttributeMaxDynamicSharedMemorySize, G16_SMEM);

    dim3 tb(32, 8);
    // 0. fp16 transposed weights [N][K]
    tr_qkv<<<dim3(3 * DM / 32, DM / 32), tb>>>(Wq, Wk, Wv, wqkvt);
    tr_plain<<<dim3(DM / 32, DM / 32), tb>>>(Wo, wot, DM, DM);
    tr_plain<<<dim3(DFF / 32, DM / 32), tb>>>(W1, w1t, DM, DFF);
    tr_plain<<<dim3(DM / 32, DFF / 32), tb>>>(W2, w2t, DFF, DM);
    // 1. h = rmsnorm(x, g1) -> fp16
    rmsnorm_kernel<<<T_, 256>>>(x, g1, h);
    // 2. fused QKV projection (fp16 mma) -> fp32 q,k,v
    tgemm16<3><<<dim3(3 * DM / 128, T_ / 128), 256, G16_SMEM>>>(
        h, wqkvt, nullptr, q, k, v, nullptr, T_, 3 * DM, DM);
    // 3. flash attention (fp16 mma) -> fp16 ctx
    attn_kernel<<<dim3(SEQ / 64, NH, BATCH), 256, ATTN_SMEM_BYTES>>>(q, k, v, ctx);
    // 4. x1 = x + ctx @ Wo (fp16 mma, fp32 out)
    tgemm16<2><<<dim3(DM / 128, T_ / 128), 256, G16_SMEM>>>(
        ctx, wot, x, x1, nullptr, nullptr, nullptr, T_, DM, DM);
    // 5. h2 = rmsnorm(x1, g2) -> fp16
    rmsnorm_kernel<<<T_, 256>>>(x1, g2, h2);
    // 6. ff = silu(h2 @ W1) -> fp16
    tgemm16<1><<<dim3(DFF / 128, T_ / 128), 256, G16_SMEM>>>(
        h2, w1t, nullptr, nullptr, nullptr, nullptr, ff, T_, DFF, DM);
    // 7. out = x1 + ff @ W2 (fp32 out)
    tgemm16<2><<<dim3(DM / 128, T_ / 128), 256, G16_SMEM>>>(
        ff, w2t, x1, out, nullptr, nullptr, nullptr, T_, DM, DFF);
}

// round 15
// speedup vs baseline: 1.5531x; 1.5531x over previous
#include <cuda_runtime.h>
#include <cuda_fp16.h>
#include <math.h>
#include <stdint.h>

#define SEQ   2048
#define BATCH 2
#define DM    1024
#define NH    16
#define HD    64
#define DFF   4096
#define T_    (SEQ*BATCH)

// ---------------- scratch (no allocations allowed) ----------------
__device__ __half g_h  [T_*DM];
__device__ __half g_q  [BATCH*NH*SEQ*HD];   // fp16, pre-scaled by 0.125
__device__ __half g_k  [BATCH*NH*SEQ*HD];
__device__ __half g_v  [BATCH*NH*SEQ*HD];
__device__ __half g_ctx[T_*DM];
__device__ float  g_x1 [T_*DM];
__device__ __half g_h2 [T_*DM];
__device__ __half g_ff [T_*DFF];
// transposed fp16 weights [N][K]
__device__ __half g_wqkvt[3*DM*DM];
__device__ __half g_wot  [DM*DM];
__device__ __half g_w1t  [DFF*DM];
__device__ __half g_w2t  [DM*DFF];

// ---------------- helpers ----------------
__device__ __forceinline__ uint32_t f2tf(float f) {
    uint32_t u;
    asm("cvt.rna.tf32.f32 %0, %1;" : "=r"(u) : "f"(f));
    return u;
}
__device__ __forceinline__ void mma_tf32(float c[4], const uint32_t a[4], const uint32_t b[2]) {
    asm volatile(
        "mma.sync.aligned.m16n8k8.row.col.f32.tf32.tf32.f32 "
        "{%0,%1,%2,%3}, {%4,%5,%6,%7}, {%8,%9}, {%0,%1,%2,%3};"
        : "+f"(c[0]), "+f"(c[1]), "+f"(c[2]), "+f"(c[3])
        : "r"(a[0]), "r"(a[1]), "r"(a[2]), "r"(a[3]), "r"(b[0]), "r"(b[1]));
}
__device__ __forceinline__ void mma_f16(float c[4], const uint32_t a[4], const uint32_t b[2]) {
    asm volatile(
        "mma.sync.aligned.m16n8k16.row.col.f32.f16.f16.f32 "
        "{%0,%1,%2,%3}, {%4,%5,%6,%7}, {%8,%9}, {%0,%1,%2,%3};"
        : "+f"(c[0]), "+f"(c[1]), "+f"(c[2]), "+f"(c[3])
        : "r"(a[0]), "r"(a[1]), "r"(a[2]), "r"(a[3]), "r"(b[0]), "r"(b[1]));
}
__device__ __forceinline__ void cp16(uint32_t dst, const void* src) {
    asm volatile("cp.async.cg.shared.global [%0], [%1], 16;" :: "r"(dst), "l"(src));
}
__device__ __forceinline__ void ldsm4(uint32_t r[4], uint32_t addr) {
    asm volatile("ldmatrix.sync.aligned.m8n8.x4.shared.b16 {%0,%1,%2,%3}, [%4];"
        : "=r"(r[0]), "=r"(r[1]), "=r"(r[2]), "=r"(r[3]) : "r"(addr));
}
__device__ __forceinline__ uint32_t h2u(__half2 h) { return *(const uint32_t*)&h; }

// ---------------- RMSNorm (fp32 in, fp16 out), vectorized ----------------
__global__ void rmsnorm_kernel(const float* __restrict__ x, const float* __restrict__ g,
                               __half* __restrict__ o) {
    int row = blockIdx.x;
    float4 v = ((const float4*)(x + (size_t)row * DM))[threadIdx.x];
    float s = v.x * v.x + v.y * v.y + v.z * v.z + v.w * v.w;
    __shared__ float red[8];
    for (int off = 16; off; off >>= 1) s += __shfl_xor_sync(0xffffffffu, s, off);
    if ((threadIdx.x & 31) == 0) red[threadIdx.x >> 5] = s;
    __syncthreads();
    if (threadIdx.x < 8) {
        float t = red[threadIdx.x];
        for (int off = 4; off; off >>= 1) t += __shfl_xor_sync(0xffu, t, off);
        if (threadIdx.x == 0) red[0] = t;
    }
    __syncthreads();
    float inv = rsqrtf(red[0] * (1.f / DM) + 1e-6f);
    float4 gv = ((const float4*)g)[threadIdx.x];
    __half2 h01 = __floats2half2_rn(gv.x * v.x * inv, gv.y * v.y * inv);
    __half2 h23 = __floats2half2_rn(gv.z * v.z * inv, gv.w * v.w * inv);
    uint2 st;
    st.x = h2u(h01);
    st.y = h2u(h23);
    *(uint2*)(o + (size_t)row * DM + threadIdx.x * 4) = st;
}

// ---------------- weight transposes (fp32 -> fp16, out[n][k] = in[k][n]) ----------------
__global__ void tr_plain(const float* __restrict__ in, __half* __restrict__ out,
                         int K, int N) {
    __shared__ float tile[32][33];
    int n0 = blockIdx.x << 5, k0 = blockIdx.y << 5;
    int tx = threadIdx.x, ty = threadIdx.y;
#pragma unroll
    for (int j = 0; j < 32; j += 8)
        tile[ty + j][tx] = in[(size_t)(k0 + ty + j) * N + n0 + tx];
    __syncthreads();
#pragma unroll
    for (int j = 0; j < 32; j += 8)
        out[(size_t)(n0 + ty + j) * K + k0 + tx] = __float2half_rn(tile[tx][ty + j]);
}
__global__ void tr_qkv(const float* __restrict__ Wq, const float* __restrict__ Wk,
                       const float* __restrict__ Wv, __half* __restrict__ out) {
    __shared__ float tile[32][33];
    int n0 = blockIdx.x << 5, k0 = blockIdx.y << 5;
    int which = n0 >> 10;
    const float* W = (which == 0) ? Wq : ((which == 1) ? Wk : Wv);
    int h = (n0 >> 6) & 15;
    int kk0 = n0 & 63;
    int tx = threadIdx.x, ty = threadIdx.y;
#pragma unroll
    for (int j = 0; j < 32; j += 8)
        tile[ty + j][tx] = W[(size_t)h * DM * HD + (size_t)(k0 + ty + j) * HD + kk0 + tx];
    __syncthreads();
#pragma unroll
    for (int j = 0; j < 32; j += 8)
        out[(size_t)(n0 + ty + j) * DM + k0 + tx] = __float2half_rn(tile[tx][ty + j]);
}

// ---- fp16 GEMM: 128x128 tile, 8 warps of 32x64, k-tile 32, cp.async + ldmatrix ----
#define PW 36
#define TILEW (128*PW)
#define G16_SMEM (4*TILEW*4)

template<int MODE>  // 1 = SiLU->half(H0), 2 = +Res->float(F0), 3 = QKV scatter->half(H0,H1,H2)
__global__ __launch_bounds__(256, 2) void tgemm16(
        const __half* __restrict__ A, const __half* __restrict__ Bt,
        const float* __restrict__ Res,
        float* __restrict__ F0,
        __half* __restrict__ H0, __half* __restrict__ H1, __half* __restrict__ H2,
        int M, int N, int Kd) {
    extern __shared__ uint32_t dsm[];
    int tid = threadIdx.x;
    int row0 = blockIdx.y << 7, col0 = blockIdx.x << 7;
    int lane = tid & 31, warp = tid >> 5;
    int wm = (warp & 3) << 5;
    int wn = (warp >> 2) << 6;
    int g = lane >> 2, t = lane & 3;

    int lr = tid >> 1;
    int lc = (tid & 1) << 1;
    const __half* Ap = A  + (size_t)(row0 + lr) * Kd + lc * 8;
    const __half* Bp = Bt + (size_t)(col0 + lr) * Kd + lc * 8;

    uint32_t s0 = (uint32_t)__cvta_generic_to_shared(dsm);
    uint32_t aoff = s0 + (lr * PW + lc * 4) * 4;
    uint32_t boff = aoff + 2 * TILEW * 4;

    uint32_t a_frag = s0 + (((wm + (lane & 15)) * PW) + ((lane >> 4) << 2)) * 4;
    uint32_t b_frag = s0 + 2 * TILEW * 4 +
                      (((wn + (lane & 7) + (((lane >> 4) & 1) << 3)) * PW) +
                       (((lane >> 3) & 1) << 2)) * 4;

    float acc[2][8][4];
#pragma unroll
    for (int i = 0; i < 2; i++)
#pragma unroll
        for (int j = 0; j < 8; j++)
#pragma unroll
            for (int v = 0; v < 4; v++) acc[i][j][v] = 0.f;

    int KT = Kd >> 5;
#pragma unroll
    for (int u = 0; u < 2; u++) {
        cp16(aoff + u * 16, Ap + u * 8);
        cp16(boff + u * 16, Bp + u * 8);
    }
    asm volatile("cp.async.commit_group;");

    for (int kt = 0; kt < KT; kt++) {
        int sel = kt & 1;
        if (kt + 1 < KT) {
            int k0 = (kt + 1) << 5;
            uint32_t ad = aoff + (sel ^ 1) * (TILEW * 4);
            uint32_t bd = boff + (sel ^ 1) * (TILEW * 4);
#pragma unroll
            for (int u = 0; u < 2; u++) {
                cp16(ad + u * 16, Ap + k0 + u * 8);
                cp16(bd + u * 16, Bp + k0 + u * 8);
            }
            asm volatile("cp.async.commit_group;");
            asm volatile("cp.async.wait_group 1;");
        } else {
            asm volatile("cp.async.wait_group 0;");
        }
        __syncthreads();
        uint32_t abase = a_frag + sel * (TILEW * 4);
        uint32_t bbase = b_frag + sel * (TILEW * 4);
#pragma unroll
        for (int ks = 0; ks < 2; ks++) {
            uint32_t kb = ks * 8 * 4;
            uint32_t af[2][4];
            ldsm4(af[0], abase + kb);
            ldsm4(af[1], abase + kb + 16 * PW * 4);
#pragma unroll
            for (int p = 0; p < 4; p++) {
                uint32_t br[4];
                ldsm4(br, bbase + kb + p * 16 * PW * 4);
                mma_f16(acc[0][2 * p],     af[0], &br[0]);
                mma_f16(acc[0][2 * p + 1], af[0], &br[2]);
                mma_f16(acc[1][2 * p],     af[1], &br[0]);
                mma_f16(acc[1][2 * p + 1], af[1], &br[2]);
            }
        }
        __syncthreads();
    }

    // epilogue
#pragma unroll
    for (int mt = 0; mt < 2; mt++) {
#pragma unroll
        for (int nt = 0; nt < 8; nt++) {
            int r = row0 + wm + mt * 16 + g;
            int c = col0 + wn + nt * 8 + t * 2;
            float2 v0 = make_float2(acc[mt][nt][0], acc[mt][nt][1]);
            float2 v1 = make_float2(acc[mt][nt][2], acc[mt][nt][3]);
            if (MODE == 3) {
                int which = c >> 10, hh = (c >> 6) & 15, kk = c & 63;
                __half* O = (which == 0) ? H0 : ((which == 1) ? H1 : H2);
                float sc = (which == 0) ? 0.125f : 1.f;   // fold softmax scale into Q
                int b = r & 1;
                int sq0 = r >> 1, sq1 = (r + 8) >> 1;
                *(__half2*)(O + ((size_t)(b * NH + hh) * SEQ + sq0) * HD + kk) =
                    __floats2half2_rn(v0.x * sc, v0.y * sc);
                *(__half2*)(O + ((size_t)(b * NH + hh) * SEQ + sq1) * HD + kk) =
                    __floats2half2_rn(v1.x * sc, v1.y * sc);
            } else if (MODE == 1) {
                float a0 = v0.x / (1.f + __expf(-v0.x));
                float a1 = v0.y / (1.f + __expf(-v0.y));
                float a2 = v1.x / (1.f + __expf(-v1.x));
                float a3 = v1.y / (1.f + __expf(-v1.y));
                *(__half2*)(H0 + (size_t)r * N + c)       = __floats2half2_rn(a0, a1);
                *(__half2*)(H0 + (size_t)(r + 8) * N + c) = __floats2half2_rn(a2, a3);
            } else {
                size_t i0 = (size_t)r * N + c;
                size_t i1 = (size_t)(r + 8) * N + c;
                float2 e0 = *(const float2*)&Res[i0];
                float2 e1 = *(const float2*)&Res[i1];
                v0.x += e0.x; v0.y += e0.y;
                v1.x += e1.x; v1.y += e1.y;
                *(float2*)&F0[i0] = v0;
                *(float2*)&F0[i1] = v1;
            }
        }
    }
}

// ---------------- flash attention on tensor cores (tf32 mma, fp16 q/k/v in gmem) ----------------
#define QP 68
#define KP 72
#define VP 72
#define SP 68
#define ATTN_SMEM_FLOATS (64*QP + 64*KP + 64*VP + 64*SP + 192)

__global__ __launch_bounds__(256, 2) void attn_kernel(
        const __half* __restrict__ Q, const __half* __restrict__ K,
        const __half* __restrict__ V, __half* __restrict__ ctx) {
    extern __shared__ float sm[];
    uint32_t* Qs  = (uint32_t*)sm;
    uint32_t* KsT = Qs + 64 * QP;
    uint32_t* Vs  = KsT + 64 * KP;
    float*    Ss  = (float*)(Vs + 64 * VP);
    float* sm_m = Ss + 64 * SP;
    float* sm_l = sm_m + 64;
    float* sm_a = sm_l + 64;

    int s0 = blockIdx.x * 64, hh = blockIdx.y, b = blockIdx.z;
    int tid = threadIdx.x;
    int lane = tid & 31, warp = tid >> 5;
    int wm = (warp & 3) << 4;
    int wn = (warp >> 2) << 5;
    int g = lane >> 2, t = lane & 3;
    const size_t bh = ((size_t)b * NH + hh) * SEQ * HD;
    const __half* Qp = Q + bh;
    const __half* Kp = K + bh;
    const __half* Vp = V + bh;

    // load Q tile (pre-scaled fp16 -> tf32 words); each thread covers 16 halves = 2 uint4
    {
        int r = tid >> 2, c4 = (tid & 3) << 4;
        uint4 q0 = *(const uint4*)&Qp[(size_t)(s0 + r) * HD + c4];
        uint4 q1 = *(const uint4*)&Qp[(size_t)(s0 + r) * HD + c4 + 8];
        const __half2* qh0 = (const __half2*)&q0;   // 4 half2 = halves c4..c4+7
        const __half2* qh1 = (const __half2*)&q1;   // 4 half2 = halves c4+8..c4+15
#pragma unroll
        for (int u = 0; u < 2; u++) {
            float2 f0 = __half22float2(qh0[2 * u]);
            float2 f1 = __half22float2(qh0[2 * u + 1]);
            uint4 v = make_uint4(f2tf(f0.x), f2tf(f0.y), f2tf(f1.x), f2tf(f1.y));
            *(uint4*)&Qs[r * QP + c4 + u * 4] = v;
        }
#pragma unroll
        for (int u = 0; u < 2; u++) {
            float2 f0 = __half22float2(qh1[2 * u]);
            float2 f1 = __half22float2(qh1[2 * u + 1]);
            uint4 v = make_uint4(f2tf(f0.x), f2tf(f0.y), f2tf(f1.x), f2tf(f1.y));
            *(uint4*)&Qs[r * QP + c4 + 8 + u * 4] = v;
        }
    }
    if (tid < 64) { sm_m[tid] = -1e30f; sm_l[tid] = 0.f; }

    float oacc[4][4];
#pragma unroll
    for (int nt = 0; nt < 4; nt++)
#pragma unroll
        for (int v = 0; v < 4; v++) oacc[nt][v] = 0.f;

    for (int j0 = 0; j0 <= s0; j0 += 64) {
        __syncthreads();
        {
            int r = tid >> 2, c4 = (tid & 3) << 4;
            // K: 16 halves -> transposed tf32
            uint4 k0r = *(const uint4*)&Kp[(size_t)(j0 + r) * HD + c4];
            uint4 k1r = *(const uint4*)&Kp[(size_t)(j0 + r) * HD + c4 + 8];
            const __half2* kh0 = (const __half2*)&k0r;
            const __half2* kh1 = (const __half2*)&k1r;
#pragma unroll
            for (int u = 0; u < 4; u++) {
                float2 f = __half22float2(kh0[u]);
                KsT[(c4 + 2 * u + 0) * KP + r] = f2tf(f.x);
                KsT[(c4 + 2 * u + 1) * KP + r] = f2tf(f.y);
            }
#pragma unroll
            for (int u = 0; u < 4; u++) {
                float2 f = __half22float2(kh1[u]);
                KsT[(c4 + 8 + 2 * u + 0) * KP + r] = f2tf(f.x);
                KsT[(c4 + 8 + 2 * u + 1) * KP + r] = f2tf(f.y);
            }
            // V: 16 halves -> row-major tf32
            uint4 v0r = *(const uint4*)&Vp[(size_t)(j0 + r) * HD + c4];
            uint4 v1r = *(const uint4*)&Vp[(size_t)(j0 + r) * HD + c4 + 8];
            const __half2* vh0 = (const __half2*)&v0r;
            const __half2* vh1 = (const __half2*)&v1r;
#pragma unroll
            for (int u = 0; u < 2; u++) {
                float2 f0 = __half22float2(vh0[2 * u]);
                float2 f1 = __half22float2(vh0[2 * u + 1]);
                uint4 vb = make_uint4(f2tf(f0.x), f2tf(f0.y), f2tf(f1.x), f2tf(f1.y));
                *(uint4*)&Vs[r * VP + c4 + u * 4] = vb;
            }
#pragma unroll
            for (int u = 0; u < 2; u++) {
                float2 f0 = __half22float2(vh1[2 * u]);
                float2 f1 = __half22float2(vh1[2 * u + 1]);
                uint4 vb = make_uint4(f2tf(f0.x), f2tf(f0.y), f2tf(f1.x), f2tf(f1.y));
                *(uint4*)&Vs[r * VP + c4 + 8 + u * 4] = vb;
            }
        }
        __syncthreads();
        float sacc[4][4];
#pragma unroll
        for (int nt = 0; nt < 4; nt++)
#pragma unroll
            for (int v = 0; v < 4; v++) sacc[nt][v] = 0.f;
#pragma unroll
        for (int ks = 0; ks < 64; ks += 8) {
            uint32_t af[4];
            af[0] = Qs[(wm + g) * QP + ks + t];
            af[1] = Qs[(wm + g + 8) * QP + ks + t];
            af[2] = Qs[(wm + g) * QP + ks + t + 4];
            af[3] = Qs[(wm + g + 8) * QP + ks + t + 4];
#pragma unroll
            for (int nt = 0; nt < 4; nt++) {
                uint32_t bf[2];
                int cb = wn + nt * 8 + g;
                bf[0] = KsT[(ks + t) * KP + cb];
                bf[1] = KsT[(ks + t + 4) * KP + cb];
                mma_tf32(sacc[nt], af, bf);
            }
        }
        {
            bool diag = (j0 == s0);
            int r0 = wm + g, r1 = wm + g + 8;
#pragma unroll
            for (int nt = 0; nt < 4; nt++) {
                int c0 = wn + nt * 8 + t * 2;
                float2 v0 = make_float2(sacc[nt][0], sacc[nt][1]);
                float2 v1 = make_float2(sacc[nt][2], sacc[nt][3]);
                if (diag) {
                    if (c0 > r0)     v0.x = -1e30f;
                    if (c0 + 1 > r0) v0.y = -1e30f;
                    if (c0 > r1)     v1.x = -1e30f;
                    if (c0 + 1 > r1) v1.y = -1e30f;
                }
                *(float2*)&Ss[r0 * SP + c0] = v0;
                *(float2*)&Ss[r1 * SP + c0] = v1;
            }
        }
        __syncthreads();
        {
            int r = tid >> 2, c0 = (tid & 3) << 4;
            float mx = -1e30f;
#pragma unroll
            for (int c = 0; c < 16; c++) mx = fmaxf(mx, Ss[r * SP + c0 + c]);
            mx = fmaxf(mx, __shfl_xor_sync(0xffffffffu, mx, 1));
            mx = fmaxf(mx, __shfl_xor_sync(0xffffffffu, mx, 2));
            float m_old = sm_m[r];
            float m_new = fmaxf(m_old, mx);
            float sum = 0.f;
#pragma unroll
            for (int c = 0; c < 16; c++) {
                float p = __expf(Ss[r * SP + c0 + c] - m_new);
                Ss[r * SP + c0 + c] = __uint_as_float(f2tf(p));
                sum += p;
            }
            sum += __shfl_xor_sync(0xffffffffu, sum, 1);
            sum += __shfl_xor_sync(0xffffffffu, sum, 2);
            if ((tid & 3) == 0) {
                float alpha = __expf(m_old - m_new);
                sm_a[r] = alpha;
                sm_m[r] = m_new;
                sm_l[r] = sm_l[r] * alpha + sum;
            }
        }
        __syncthreads();
        {
            float al0 = sm_a[wm + g], al1 = sm_a[wm + g + 8];
#pragma unroll
            for (int nt = 0; nt < 4; nt++) {
                oacc[nt][0] *= al0; oacc[nt][1] *= al0;
                oacc[nt][2] *= al1; oacc[nt][3] *= al1;
            }
        }
#pragma unroll
        for (int ks = 0; ks < 64; ks += 8) {
            uint32_t af[4];
            af[0] = __float_as_uint(Ss[(wm + g) * SP + ks + t]);
            af[1] = __float_as_uint(Ss[(wm + g + 8) * SP + ks + t]);
            af[2] = __float_as_uint(Ss[(wm + g) * SP + ks + t + 4]);
            af[3] = __float_as_uint(Ss[(wm + g + 8) * SP + ks + t + 4]);
#pragma unroll
            for (int nt = 0; nt < 4; nt++) {
                uint32_t bf[2];
                int cb = wn + nt * 8 + g;
                bf[0] = Vs[(ks + t) * VP + cb];
                bf[1] = Vs[(ks + t + 4) * VP + cb];
                mma_tf32(oacc[nt], af, bf);
            }
        }
    }
    {
        float inv0 = 1.f / sm_l[wm + g];
        float inv1 = 1.f / sm_l[wm + g + 8];
        int r0 = s0 + wm + g, r1 = s0 + wm + g + 8;
#pragma unroll
        for (int nt = 0; nt < 4; nt++) {
            int c0 = hh * HD + wn + nt * 8 + t * 2;
            *(__half2*)&ctx[((size_t)r0 * BATCH + b) * DM + c0] =
                __floats2half2_rn(oacc[nt][0] * inv0, oacc[nt][1] * inv0);
            *(__half2*)&ctx[((size_t)r1 * BATCH + b) * DM + c0] =
                __floats2half2_rn(oacc[nt][2] * inv1, oacc[nt][3] * inv1);
        }
    }
}

// ---------------- launch ----------------
extern "C" void kernel_launch(void* const* d_in, const int* in_sizes, int n_in,
                              void* d_out, int out_size) {
    const float* x  = (const float*)d_in[0];
    const float* g1 = (const float*)d_in[1];
    const float* g2 = (const float*)d_in[2];
    const float* Wq = (const float*)d_in[3];
    const float* Wk = (const float*)d_in[4];
    const float* Wv = (const float*)d_in[5];
    const float* Wo = (const float*)d_in[6];
    const float* W1 = (const float*)d_in[7];
    const float* W2 = (const float*)d_in[8];
    float* out = (float*)d_out;

    __half *h, *q, *k, *v, *ctx, *h2, *ff, *wqkvt, *wot, *w1t, *w2t;
    float *x1;
    cudaGetSymbolAddress((void**)&h,   g_h);
    cudaGetSymbolAddress((void**)&q,   g_q);
    cudaGetSymbolAddress((void**)&k,   g_k);
    cudaGetSymbolAddress((void**)&v,   g_v);
    cudaGetSymbolAddress((void**)&ctx, g_ctx);
    cudaGetSymbolAddress((void**)&x1,  g_x1);
    cudaGetSymbolAddress((void**)&h2,  g_h2);
    cudaGetSymbolAddress((void**)&ff,  g_ff);
    cudaGetSymbolAddress((void**)&wqkvt, g_wqkvt);
    cudaGetSymbolAddress((void**)&wot,   g_wot);
    cudaGetSymbolAddress((void**)&w1t,   g_w1t);
    cudaGetSymbolAddress((void**)&w2t,   g_w2t);

    const int attn_smem = ATTN_SMEM_FLOATS * 4;
    cudaFuncSetAttribute(attn_kernel, cudaFuncAttributeMaxDynamicSharedMemorySize, attn_smem);
    cudaFuncSetAttribute(tgemm16<1>, cudaFuncAttributeMaxDynamicSharedMemorySize, G16_SMEM);
    cudaFuncSetAttribute(tgemm16<2>, cudaFuncAttributeMaxDynamicSharedMemorySize, G16_SMEM);
    cudaFuncSetAttribute(tgemm16<3>, cudaFuncAttributeMaxDynamicSharedMemorySize, G16_SMEM);

    dim3 tb(32, 8);
    // 0. fp16 transposed weights [N][K]
    tr_qkv<<<dim3(3 * DM / 32, DM / 32), tb>>>(Wq, Wk, Wv, wqkvt);
    tr_plain<<<dim3(DM / 32, DM / 32), tb>>>(Wo, wot, DM, DM);
    tr_plain<<<dim3(DFF / 32, DM / 32), tb>>>(W1, w1t, DM, DFF);
    tr_plain<<<dim3(DM / 32, DFF / 32), tb>>>(W2, w2t, DFF, DM);
    // 1. h = rmsnorm(x, g1) -> fp16
    rmsnorm_kernel<<<T_, 256>>>(x, g1, h);
    // 2. fused QKV projection (fp16 mma) -> fp16 q(scaled),k,v
    tgemm16<3><<<dim3(3 * DM / 128, T_ / 128), 256, G16_SMEM>>>(
        h, wqkvt, nullptr, nullptr, q, k, v, T_, 3 * DM, DM);
    // 3. flash attention (tf32 mma, fp16 inputs) -> fp16 ctx
    attn_kernel<<<dim3(SEQ / 64, NH, BATCH), 256, attn_smem>>>(q, k, v, ctx);
    // 4. x1 = x + ctx @ Wo (fp16 mma, fp32 out)
    tgemm16<2><<<dim3(DM / 128, T_ / 128), 256, G16_SMEM>>>(
        ctx, wot, x, x1, nullptr, nullptr, nullptr, T_, DM, DM);
    // 5. h2 = rmsnorm(x1, g2) -> fp16
    rmsnorm_kernel<<<T_, 256>>>(x1, g2, h2);
    // 6. ff = silu(h2 @ W1) -> fp16
    tgemm16<1><<<dim3(DFF / 128, T_ / 128), 256, G16_SMEM>>>(
        h2, w1t, nullptr, nullptr, ff, nullptr, nullptr, T_, DFF, DM);
    // 7. out = x1 + ff @ W2 (fp32 out)
    tgemm16<2><<<dim3(DM / 128, T_ / 128), 256, G16_SMEM>>>(
        ff, w2t, x1, out, nullptr, nullptr, nullptr, T_, DM, DFF);
}